// round 6
// baseline (speedup 1.0000x reference)
#include <cuda_runtime.h>
#include <cuda_bf16.h>
#include <math.h>
#include <stdint.h>

// ---------------------------------------------------------------------------
// dividedSpaceTimeAttention — packed-f32x2 SIMT GEMM version.
// Finding: on this harness (compute_103, non-'a'), tcgen05 is rejected and
// mma.sync is emulated on the FMA pipe (~34 TF/s). So: single-pass fp32 GEMM
// using fma.rn.f32x2 (FFMA2) to double the FFMA roofline.
// ---------------------------------------------------------------------------

#define Bc    8
#define NHc   12
#define DIMc  768
#define NPc   196
#define NFc   16
#define D3c   192
#define SEQ1  3137
#define N3D   2304
#define MROWS (Bc*SEQ1)     // 25096
#define SCALEc (1.0f/96.0f)

typedef unsigned long long ull;

// -------------------- static scratch ---------------------------------------
__device__ float g_Pq[MROWS * N3D];
__device__ float g_Pk[MROWS * N3D];
__device__ float g_Pv[MROWS * N3D];
__device__ float g_tmp[Bc * 195 * N3D];
__device__ float g_ti [Bc * 195 * DIMc];
__device__ float g_q2u[Bc * 195 * N3D];
__device__ float g_k2u[Bc * 195 * N3D];
__device__ float g_v2u[Bc * 195 * N3D];
__device__ float g_t2cat[Bc * 17 * N3D];
__device__ float g_outsmall[Bc * 17 * DIMc];

// ===================== f32x2 helpers =======================================
__device__ __forceinline__ ull pack2(float x, float y) {
    ull r;
    asm("mov.b64 %0, {%1, %2};" : "=l"(r) : "f"(x), "f"(y));
    return r;
}
__device__ __forceinline__ void ffma2(ull& d, ull a, ull b) {
    asm("fma.rn.f32x2 %0, %1, %2, %0;" : "+l"(d) : "l"(a), "l"(b));
}
__device__ __forceinline__ float lo32(ull v) { return __uint_as_float((uint32_t)v); }
__device__ __forceinline__ float hi32(ull v) { return __uint_as_float((uint32_t)(v >> 32)); }

// ===================== packed-f32x2 GEMM ===================================
// C(z) = A(MxK) @ W(z)(KxN) + bias(z).  W natural [K][N] layout.
// Tile 128x128, BK=16, 256 threads, TM=TN=8.
// acc pairs packed along M; B duplicated in SMEM so LDS.128 yields broadcast pairs.
#define GBM 128
#define GBN 128
#define GBK 16
// per-buffer floats: As 16*128 = 2048, Bdup 16*256 = 4096
#define SH_B 2048
#define SH_BUF 6144

__global__ __launch_bounds__(256, 2)
void gemm_f32x2(const float* __restrict__ A,
                const float* __restrict__ W0, const float* __restrict__ W1, const float* __restrict__ W2,
                const float* __restrict__ b0v, const float* __restrict__ b1v, const float* __restrict__ b2v,
                float* __restrict__ C0, float* __restrict__ C1, float* __restrict__ C2,
                int M, int N, int K)
{
    __shared__ float sh[2][SH_BUF];   // 48 KB

    const int tid = threadIdx.x;
    const int tx = tid & 15;          // N direction
    const int ty = tid >> 4;          // M direction

    const int z = blockIdx.z;
    const float* W    = (z == 0) ? W0  : (z == 1) ? W1  : W2;
    const float* bias = (z == 0) ? b0v : (z == 1) ? b1v : b2v;
    float*       C    = (z == 0) ? C0  : (z == 1) ? C1  : C2;

    const int bm = blockIdx.y * GBM;
    const int bn = blockIdx.x * GBN;
    const int NC = K / GBK;

    // stage registers
    float4 ra[2], rb[2];

    // A tasks: s = tid + 256*i; m = s>>2 (0..127), quad = s&3 (k-quad)
    // B tasks: k = s>>5 (0..15), quad = s&31 (n-quad)  -> 128B coalesced
    auto ldg_chunk = [&](int c) {
        const int k0 = c * GBK;
        #pragma unroll
        for (int i = 0; i < 2; i++) {
            const int s = tid + i * 256;
            const int mA = s >> 2, qA = s & 3;
            const int gr = bm + mA;
            ra[i] = (gr < M) ? *reinterpret_cast<const float4*>(&A[(size_t)gr * K + k0 + qA * 4])
                             : make_float4(0.f, 0.f, 0.f, 0.f);
            const int kB = s >> 5, qB = s & 31;
            rb[i] = *reinterpret_cast<const float4*>(&W[(size_t)(k0 + kB) * N + bn + qB * 4]);
        }
    };
    auto sts_chunk = [&](int buf) {
        float* As = sh[buf];
        float* Bd = sh[buf] + SH_B;
        #pragma unroll
        for (int i = 0; i < 2; i++) {
            const int s = tid + i * 256;
            const int mA = s >> 2, qA = s & 3;
            As[(qA * 4 + 0) * 128 + mA] = ra[i].x;
            As[(qA * 4 + 1) * 128 + mA] = ra[i].y;
            As[(qA * 4 + 2) * 128 + mA] = ra[i].z;
            As[(qA * 4 + 3) * 128 + mA] = ra[i].w;
            const int kB = s >> 5, qB = s & 31;
            float* p = &Bd[kB * 256 + qB * 8];
            *reinterpret_cast<float4*>(p)     = make_float4(rb[i].x, rb[i].x, rb[i].y, rb[i].y);
            *reinterpret_cast<float4*>(p + 4) = make_float4(rb[i].z, rb[i].z, rb[i].w, rb[i].w);
        }
    };

    ull acc[4][8];
    #pragma unroll
    for (int p = 0; p < 4; p++)
        #pragma unroll
        for (int j = 0; j < 8; j++) acc[p][j] = 0ull;

    ldg_chunk(0);
    sts_chunk(0);
    __syncthreads();

    for (int c = 0; c < NC; c++) {
        if (c + 1 < NC) ldg_chunk(c + 1);

        const float* As = sh[c & 1];
        const float* Bd = sh[c & 1] + SH_B;

        #pragma unroll
        for (int kk = 0; kk < GBK; kk++) {
            // A: 8 contiguous rows ty*8.. -> 4 packed (m,m+1) pairs
            const float4 a0 = *reinterpret_cast<const float4*>(&As[kk * 128 + ty * 8]);
            const float4 a1 = *reinterpret_cast<const float4*>(&As[kk * 128 + ty * 8 + 4]);
            ull a2[4];
            a2[0] = pack2(a0.x, a0.y);
            a2[1] = pack2(a0.z, a0.w);
            a2[2] = pack2(a1.x, a1.y);
            a2[3] = pack2(a1.z, a1.w);
            // B: 4 groups of duplicated pairs; cols n = g*32 + tx*2 + {0,1}
            ull b2[8];
            #pragma unroll
            for (int g = 0; g < 4; g++) {
                const float4 bv = *reinterpret_cast<const float4*>(&Bd[kk * 256 + g * 64 + tx * 4]);
                b2[2 * g]     = pack2(bv.x, bv.y);   // {v(n), v(n)}
                b2[2 * g + 1] = pack2(bv.z, bv.w);   // {v(n+1), v(n+1)}
            }
            #pragma unroll
            for (int p = 0; p < 4; p++)
                #pragma unroll
                for (int j = 0; j < 8; j++)
                    ffma2(acc[p][j], a2[p], b2[j]);
        }
        __syncthreads();
        if (c + 1 < NC) {
            sts_chunk((c + 1) & 1);
            __syncthreads();
        }
    }

    // ---- epilogue: rows bm+ty*8+2p(+1), cols g*32+tx*2(+1) ----
    #pragma unroll
    for (int p = 0; p < 4; p++) {
        const int r0 = bm + ty * 8 + 2 * p;
        #pragma unroll
        for (int g = 0; g < 4; g++) {
            const int col = bn + g * 32 + tx * 2;
            const float bx = bias[col], by = bias[col + 1];
            if (r0 < M) {
                float2 o = make_float2(lo32(acc[p][2 * g]) + bx, lo32(acc[p][2 * g + 1]) + by);
                *reinterpret_cast<float2*>(&C[(size_t)r0 * N + col]) = o;
            }
            if (r0 + 1 < M) {
                float2 o = make_float2(hi32(acc[p][2 * g]) + bx, hi32(acc[p][2 * g + 1]) + by);
                *reinterpret_cast<float2*>(&C[(size_t)(r0 + 1) * N + col]) = o;
            }
        }
    }
}

// ===================== attention kernels (passing since R2) ================
__global__ __launch_bounds__(256)
void temporal_kernel(const float* __restrict__ Pq, const float* __restrict__ Pk,
                     const float* __restrict__ Pv, float* __restrict__ tmpf)
{
    const int p = blockIdx.x + 1;
    const int b = blockIdx.y / NHc;
    const int h = blockIdx.y % NHc;
    const int tid = threadIdx.x;

    __shared__ float qs[NFc][D3c + 1];
    __shared__ float ks[NFc][D3c + 1];
    __shared__ float vs[NFc][D3c + 1];
    __shared__ float logits[NFc][NFc + 1];
    __shared__ float colw[NFc];

    for (int e = tid; e < NFc * 96; e += 256) {
        const int f = e / 96;
        const int i = e % 96;
        const int t = f * NPc + p;
        const size_t base = ((size_t)(b * SEQ1 + 1 + t)) * N3D + h * D3c + 2 * i;
        float q0 = Pq[base], q1 = Pq[base + 1];
        float k0 = Pv[base], k1 = Pv[base + 1];
        const float v0 = Pk[base], v1 = Pk[base + 1];
        if (i < 32) {
            const double invf = pow(10000.0, -(double)(2 * i) / 64.0);
            const double a = (double)t * invf;
            const float c = (float)cos(a);
            const float s = (float)sin(a);
            const float nq0 = q0 * c - q1 * s, nq1 = q1 * c + q0 * s;
            const float nk0 = k0 * c - k1 * s, nk1 = k1 * c + k0 * s;
            q0 = nq0; q1 = nq1; k0 = nk0; k1 = nk1;
        }
        qs[f][2 * i] = q0; qs[f][2 * i + 1] = q1;
        ks[f][2 * i] = k0; ks[f][2 * i + 1] = k1;
        vs[f][2 * i] = v0; vs[f][2 * i + 1] = v1;
    }
    __syncthreads();

    {
        const int f = tid >> 4, g = tid & 15;
        float d = 0.f;
        #pragma unroll 8
        for (int e = 0; e < D3c; e++) d += qs[f][e] * ks[g][e];
        logits[f][g] = d * SCALEc;
    }
    __syncthreads();

    if (tid < NFc) {
        const int f = tid;
        float m = -1e30f;
        #pragma unroll
        for (int g = 0; g < NFc; g++) m = fmaxf(m, logits[f][g]);
        float l = 0.f;
        #pragma unroll
        for (int g = 0; g < NFc; g++) l += expf(logits[f][g] - m);
        const float inv = 1.f / l;
        #pragma unroll
        for (int g = 0; g < NFc; g++) logits[f][g] = expf(logits[f][g] - m) * inv;
    }
    __syncthreads();

    if (tid < NFc) {
        const int g = tid;
        float s = 0.f;
        #pragma unroll
        for (int f = 0; f < NFc; f++) s += logits[f][g];
        colw[g] = s;
    }
    __syncthreads();

    if (tid < D3c) {
        const int d = tid;
        float a = 0.f;
        #pragma unroll
        for (int g = 0; g < NFc; g++) a += colw[g] * vs[g][d];
        tmpf[((size_t)(b * 195 + (p - 1))) * N3D + h * D3c + d] = a;
    }
}

__global__ __launch_bounds__(256)
void cls_kernel(const float* __restrict__ Pq, const float* __restrict__ Pk,
                const float* __restrict__ Pv, float* __restrict__ t2cat)
{
    const int b = blockIdx.x / NHc;
    const int h = blockIdx.x % NHc;
    const int tid = threadIdx.x;

    __shared__ float logits[SEQ1];
    __shared__ float qv[D3c];
    __shared__ float red[256];

    if (tid < D3c) qv[tid] = Pq[((size_t)(b * SEQ1)) * N3D + h * D3c + tid];
    __syncthreads();

    float lmax = -1e30f;
    for (int s = tid; s < SEQ1; s += 256) {
        const float* kr = Pk + ((size_t)(b * SEQ1 + s)) * N3D + h * D3c;
        float d = 0.f;
        #pragma unroll 8
        for (int e = 0; e < D3c; e++) d += qv[e] * kr[e];
        d *= SCALEc;
        logits[s] = d;
        lmax = fmaxf(lmax, d);
    }
    red[tid] = lmax; __syncthreads();
    for (int o = 128; o > 0; o >>= 1) { if (tid < o) red[tid] = fmaxf(red[tid], red[tid + o]); __syncthreads(); }
    const float M = red[0];
    __syncthreads();

    float lsum = 0.f;
    for (int s = tid; s < SEQ1; s += 256) {
        const float w = expf(logits[s] - M);
        logits[s] = w;
        lsum += w;
    }
    red[tid] = lsum; __syncthreads();
    for (int o = 128; o > 0; o >>= 1) { if (tid < o) red[tid] += red[tid + o]; __syncthreads(); }
    const float inv = 1.f / red[0];
    __syncthreads();

    if (tid < D3c) {
        float a = 0.f;
        for (int s = 0; s < SEQ1; s++)
            a += logits[s] * Pv[((size_t)(b * SEQ1 + s)) * N3D + h * D3c + tid];
        t2cat[((size_t)(b * 17)) * N3D + h * D3c + tid] = a * inv;
    }
}

__global__ __launch_bounds__(256)
void spatial_kernel(const float* __restrict__ q2u, const float* __restrict__ k2u,
                    const float* __restrict__ v2u, float* __restrict__ t2cat)
{
    const int xi = blockIdx.x;
    const int b = blockIdx.y / NHc;
    const int h = blockIdx.y % NHc;
    const int tid = threadIdx.x;
    const int warp = tid >> 5, lane = tid & 31;
    const int nk = (xi == 0) ? 196 : 16;
    const int hb = h * D3c;

    __shared__ float wsh[8][200];
    __shared__ float wacc[8][D3c];

    for (int e = tid; e < 8 * D3c; e += 256) wacc[e / D3c][e % D3c] = 0.f;
    __syncthreads();

    for (int q0 = warp; q0 < 196; q0 += 8) {
        const int qp = (xi + q0) % 195;
        const float* qr = q2u + ((size_t)(b * 195 + qp)) * N3D + hb;

        float lg[7];
        float lmax = -1e30f;
        int cnt = 0;
        for (int m = lane; m < nk; m += 32) {
            const int kp = (xi == 0) ? (m % 195) : ((xi + m) % 195);
            const float* kr = k2u + ((size_t)(b * 195 + kp)) * N3D + hb;
            float d = 0.f;
            #pragma unroll 8
            for (int e = 0; e < D3c; e++) d += qr[e] * kr[e];
            lg[cnt++] = d * SCALEc;
            lmax = fmaxf(lmax, d * SCALEc);
        }
        #pragma unroll
        for (int o = 16; o > 0; o >>= 1) lmax = fmaxf(lmax, __shfl_xor_sync(0xffffffffu, lmax, o));
        float lsum = 0.f;
        for (int c = 0; c < cnt; c++) { lg[c] = expf(lg[c] - lmax); lsum += lg[c]; }
        #pragma unroll
        for (int o = 16; o > 0; o >>= 1) lsum += __shfl_xor_sync(0xffffffffu, lsum, o);
        const float inv = 1.f / lsum;
        cnt = 0;
        for (int m = lane; m < nk; m += 32) wsh[warp][m] = lg[cnt++] * inv;
        __syncwarp();

        for (int dd = lane; dd < D3c; dd += 32) {
            float a = 0.f;
            for (int m = 0; m < nk; m++) {
                const int kp = (xi == 0) ? (m % 195) : ((xi + m) % 195);
                a += wsh[warp][m] * v2u[((size_t)(b * 195 + kp)) * N3D + hb + dd];
            }
            wacc[warp][dd] += a;
        }
        __syncwarp();
    }
    __syncthreads();

    if (tid < D3c) {
        float s = 0.f;
        #pragma unroll
        for (int wp = 0; wp < 8; wp++) s += wacc[wp][tid];
        t2cat[((size_t)(b * 17) + 1 + xi) * N3D + hb + tid] = s;
    }
}

__global__ void broadcast_kernel(const float* __restrict__ outsmall, float* __restrict__ out)
{
    const size_t i = (size_t)blockIdx.x * blockDim.x + threadIdx.x;
    const size_t total = (size_t)Bc * SEQ1 * DIMc;
    if (i >= total) return;
    const int c = (int)(i % DIMc);
    const size_t bs = i / DIMc;
    const int s = (int)(bs % SEQ1);
    const int b = (int)(bs / SEQ1);
    const int r = (s == 0) ? 0 : (1 + ((s - 1) & 15));
    out[i] = outsmall[((size_t)(b * 17) + r) * DIMc + c];
}

// ===================== launch ==============================================
extern "C" void kernel_launch(void* const* d_in, const int* in_sizes, int n_in,
                              void* d_out, int out_size)
{
    const float* x  = (const float*)d_in[0];
    const float* Wq = (const float*)d_in[1];
    const float* bq = (const float*)d_in[2];
    const float* Wk = (const float*)d_in[3];
    const float* bk = (const float*)d_in[4];
    const float* Wv = (const float*)d_in[5];
    const float* bv = (const float*)d_in[6];
    const float* Wt = (const float*)d_in[7];
    const float* bt = (const float*)d_in[8];
    const float* Wf = (const float*)d_in[9];
    const float* bf = (const float*)d_in[10];
    float* out = (float*)d_out;

    float *Pq, *Pk, *Pv, *tmpf, *ti, *q2u, *k2u, *v2u, *t2cat, *outsmall;
    cudaGetSymbolAddress((void**)&Pq, g_Pq);
    cudaGetSymbolAddress((void**)&Pk, g_Pk);
    cudaGetSymbolAddress((void**)&Pv, g_Pv);
    cudaGetSymbolAddress((void**)&tmpf, g_tmp);
    cudaGetSymbolAddress((void**)&ti, g_ti);
    cudaGetSymbolAddress((void**)&q2u, g_q2u);
    cudaGetSymbolAddress((void**)&k2u, g_k2u);
    cudaGetSymbolAddress((void**)&v2u, g_v2u);
    cudaGetSymbolAddress((void**)&t2cat, g_t2cat);
    cudaGetSymbolAddress((void**)&outsmall, g_outsmall);

    const dim3 blk(256);

    // 1) QKV projections (fused 3-in-1)
    gemm_f32x2<<<dim3(N3D / GBN, (MROWS + GBM - 1) / GBM, 3), blk>>>(
        x, Wq, Wk, Wv, bq, bk, bv, Pq, Pk, Pv, MROWS, N3D, DIMc);

    // 2) temporal + cls attention
    temporal_kernel<<<dim3(195, Bc * NHc), blk>>>(Pq, Pk, Pv, tmpf);
    cls_kernel<<<Bc * NHc, blk>>>(Pq, Pk, Pv, t2cat);

    // 3) ti = tmp @ Wt + bt   (195 unique rows per batch)
    gemm_f32x2<<<dim3(DIMc / GBN, (Bc * 195 + GBM - 1) / GBM, 1), blk>>>(
        tmpf, Wt, Wt, Wt, bt, bt, bt, ti, ti, ti, Bc * 195, DIMc, N3D);

    // 4) second-stage projections (fused 3-in-1; crossed k/v per reference)
    gemm_f32x2<<<dim3(N3D / GBN, (Bc * 195 + GBM - 1) / GBM, 3), blk>>>(
        ti, Wq, Wv, Wk, bq, bv, bk, q2u, k2u, v2u, Bc * 195, N3D, DIMc);

    // 5) spatial attention
    spatial_kernel<<<dim3(16, Bc * NHc), blk>>>(q2u, k2u, v2u, t2cat);

    // 6) final projection of 17 unique rows per batch
    gemm_f32x2<<<dim3(DIMc / GBN, (Bc * 17 + GBM - 1) / GBM, 1), blk>>>(
        t2cat, Wf, Wf, Wf, bf, bf, bf, outsmall, outsmall, outsmall, Bc * 17, DIMc, N3D);

    // 7) broadcast to full output
    const size_t total = (size_t)Bc * SEQ1 * DIMc;
    broadcast_kernel<<<(unsigned)((total + 255) / 256), blk>>>(outsmall, out);
}

// round 7
// speedup vs baseline: 1.9009x; 1.9009x over previous
#include <cuda_runtime.h>
#include <cuda_bf16.h>
#include <math.h>
#include <stdint.h>

// ---------------------------------------------------------------------------
// dividedSpaceTimeAttention — pre-split bf16 + cp.async + mma.sync pipeline.
// R5 proved mma.sync reaches real HMMA on this target; this round strips the
// fp32->bf16 conversion out of the GEMM hot loop and deepens the pipeline.
// ---------------------------------------------------------------------------

#define Bc    8
#define NHc   12
#define DIMc  768
#define NPc   196
#define NFc   16
#define D3c   192
#define SEQ1  3137
#define N3D   2304
#define MROWS (Bc*SEQ1)     // 25096
#define SCALEc (1.0f/96.0f)

// -------------------- static scratch ---------------------------------------
__device__ float g_Pq[MROWS * N3D];
__device__ float g_Pk[MROWS * N3D];
__device__ float g_Pv[MROWS * N3D];
__device__ float g_tmp[Bc * 195 * N3D];
__device__ float g_ti [Bc * 195 * DIMc];
__device__ float g_q2u[Bc * 195 * N3D];
__device__ float g_k2u[Bc * 195 * N3D];
__device__ float g_v2u[Bc * 195 * N3D];
__device__ float g_t2cat[Bc * 17 * N3D];
__device__ float g_outsmall[Bc * 17 * DIMc];

// pre-split bf16 activations (hi/lo), reused across stages (max = x)
__device__ __nv_bfloat16 g_Ah[MROWS * DIMc];
__device__ __nv_bfloat16 g_Al[MROWS * DIMc];
// pre-split + transposed weights [N][K] bf16 hi/lo
__device__ __nv_bfloat16 g_Wqh[N3D * DIMc], g_Wql[N3D * DIMc];
__device__ __nv_bfloat16 g_Wkh[N3D * DIMc], g_Wkl[N3D * DIMc];
__device__ __nv_bfloat16 g_Wvh[N3D * DIMc], g_Wvl[N3D * DIMc];
__device__ __nv_bfloat16 g_Wth[DIMc * N3D], g_Wtl[DIMc * N3D];
__device__ __nv_bfloat16 g_Wfh[DIMc * N3D], g_Wfl[DIMc * N3D];

__device__ __forceinline__ uint32_t smem_u32(const void* p) {
    uint32_t a;
    asm("{ .reg .u64 t; cvta.to.shared.u64 t, %1; cvt.u32.u64 %0, t; }" : "=r"(a) : "l"(p));
    return a;
}
__device__ __forceinline__ void cp16(uint32_t dst, const void* src) {
    asm volatile("cp.async.cg.shared.global [%0], [%1], 16;" :: "r"(dst), "l"(src));
}
#define CP_COMMIT() asm volatile("cp.async.commit_group;" ::: "memory")
#define CP_WAIT1()  asm volatile("cp.async.wait_group 1;" ::: "memory")

__device__ __forceinline__ void ldm_x4(uint32_t* r, uint32_t addr) {
    asm volatile("ldmatrix.sync.aligned.m8n8.x4.shared.b16 {%0,%1,%2,%3}, [%4];"
                 : "=r"(r[0]), "=r"(r[1]), "=r"(r[2]), "=r"(r[3]) : "r"(addr));
}
__device__ __forceinline__ void mma_bf16(float* d, const uint32_t* a, uint32_t b0, uint32_t b1) {
    asm volatile("mma.sync.aligned.m16n8k16.row.col.f32.bf16.bf16.f32 "
                 "{%0,%1,%2,%3}, {%4,%5,%6,%7}, {%8,%9}, {%0,%1,%2,%3};"
                 : "+f"(d[0]), "+f"(d[1]), "+f"(d[2]), "+f"(d[3])
                 : "r"(a[0]), "r"(a[1]), "r"(a[2]), "r"(a[3]), "r"(b0), "r"(b1));
}

// ===================== prep kernels ========================================
// split fp32 -> hi/lo bf16 (vectorized by 4)
__global__ __launch_bounds__(256)
void split_f32(const float* __restrict__ s, __nv_bfloat16* __restrict__ h,
               __nv_bfloat16* __restrict__ l, int n4)
{
    const int i = blockIdx.x * 256 + threadIdx.x;
    if (i >= n4) return;
    const float4 v = reinterpret_cast<const float4*>(s)[i];
    __nv_bfloat162 h01 = __floats2bfloat162_rn(v.x, v.y);
    __nv_bfloat162 h23 = __floats2bfloat162_rn(v.z, v.w);
    __nv_bfloat162 l01 = __floats2bfloat162_rn(v.x - __bfloat162float(h01.x),
                                               v.y - __bfloat162float(h01.y));
    __nv_bfloat162 l23 = __floats2bfloat162_rn(v.z - __bfloat162float(h23.x),
                                               v.w - __bfloat162float(h23.y));
    reinterpret_cast<__nv_bfloat162*>(h)[2 * i]     = h01;
    reinterpret_cast<__nv_bfloat162*>(h)[2 * i + 1] = h23;
    reinterpret_cast<__nv_bfloat162*>(l)[2 * i]     = l01;
    reinterpret_cast<__nv_bfloat162*>(l)[2 * i + 1] = l23;
}

// W[K][N] fp32 -> WT[N][K] bf16 hi/lo
__global__ __launch_bounds__(256)
void transpose_split(const float* __restrict__ W, __nv_bfloat16* __restrict__ hT,
                     __nv_bfloat16* __restrict__ lT, int K, int N)
{
    __shared__ float t[32][33];
    const int k0 = blockIdx.x * 32, n0 = blockIdx.y * 32;
    const int x = threadIdx.x & 31, y = (threadIdx.x >> 5) * 4;
    #pragma unroll
    for (int j = 0; j < 4; j++)
        t[y + j][x] = W[(size_t)(k0 + y + j) * N + n0 + x];
    __syncthreads();
    #pragma unroll
    for (int j = 0; j < 4; j++) {
        const int n = n0 + y + j, k = k0 + x;
        const float v = t[x][y + j];
        const __nv_bfloat16 h = __float2bfloat16_rn(v);
        hT[(size_t)n * K + k] = h;
        lT[(size_t)n * K + k] = __float2bfloat16_rn(v - __bfloat162float(h));
    }
}

// ===================== bf16-split mma.sync GEMM ============================
// C(z) = A @ W(z)^T + bias(z);  A hi/lo [M][K] bf16, W hi/lo [N][K] bf16.
// Tile 128x128x32, 8 warps (4 M x 2 N), 3-stage cp.async pipeline.
// Swizzled smem: off(row,c16) = row*64 + ((c16 ^ ((row>>1)&3))*16).
#define GBM 128
#define GBN 128
#define GBK 32
#define STG_B 32768             // 4 matrices * 128*64B
#define MAT_B 8192
#define GEMM_SMEM (3 * STG_B)   // 98304

__global__ __launch_bounds__(256, 2)
void gemm_bf16s(const __nv_bfloat16* __restrict__ Ah, const __nv_bfloat16* __restrict__ Al,
                const __nv_bfloat16* __restrict__ Wh0, const __nv_bfloat16* __restrict__ Wl0,
                const __nv_bfloat16* __restrict__ Wh1, const __nv_bfloat16* __restrict__ Wl1,
                const __nv_bfloat16* __restrict__ Wh2, const __nv_bfloat16* __restrict__ Wl2,
                const float* __restrict__ b0v, const float* __restrict__ b1v, const float* __restrict__ b2v,
                float* __restrict__ C0, float* __restrict__ C1, float* __restrict__ C2,
                int M, int N, int K)
{
    extern __shared__ char sb[];
    const uint32_t sb32 = smem_u32(sb);

    const int tid = threadIdx.x;
    const int lane = tid & 31;
    const int wid = tid >> 5;
    const int wm = wid & 3;
    const int wn = wid >> 2;

    const int z = blockIdx.z;
    const __nv_bfloat16* Wh = (z == 0) ? Wh0 : (z == 1) ? Wh1 : Wh2;
    const __nv_bfloat16* Wl = (z == 0) ? Wl0 : (z == 1) ? Wl1 : Wl2;
    const float* bias = (z == 0) ? b0v : (z == 1) ? b1v : b2v;
    float*       C    = (z == 0) ? C0  : (z == 1) ? C1  : C2;

    const int bm = blockIdx.y * GBM;
    const int bn = blockIdx.x * GBN;
    const int NC = K / GBK;

    // loader mapping: 1024 tasks of 16B; mat = s>>9, r = (s>>2)&127, c16 = s&3
    auto load_stage = [&](int stage, int c) {
        const int k0 = c * GBK;
        const uint32_t sbase = sb32 + (uint32_t)(stage * STG_B);
        #pragma unroll
        for (int i = 0; i < 4; i++) {
            const int s = tid + i * 256;
            const int r = (s >> 2) & 127;
            const int c16 = s & 3;
            const uint32_t doff = (uint32_t)(r * 64 + ((c16 ^ ((r >> 1) & 3)) * 16));
            int gr = bm + r; if (gr >= M) gr = M - 1;
            const size_t ga = (size_t)gr * K + k0 + c16 * 8;
            cp16(sbase + 0 * MAT_B + doff, Ah + ga);
            cp16(sbase + 1 * MAT_B + doff, Al + ga);
            const size_t gb = (size_t)(bn + r) * K + k0 + c16 * 8;
            cp16(sbase + 2 * MAT_B + doff, Wh + gb);
            cp16(sbase + 3 * MAT_B + doff, Wl + gb);
        }
    };

    float acc[2][8][4];
    #pragma unroll
    for (int i = 0; i < 2; i++)
        #pragma unroll
        for (int j = 0; j < 8; j++)
            #pragma unroll
            for (int q = 0; q < 4; q++) acc[i][j][q] = 0.f;

    // per-lane fragment address components
    const int rowA = wm * 32 + (lane & 15);
    const int kha  = lane >> 4;                 // A k-half
    const int xorA = (rowA >> 1) & 3;           // invariant under +16
    const int bgrp = lane >> 3;
    const int rowB = wn * 64 + (bgrp >> 1) * 8 + (lane & 7);
    const int khb  = bgrp & 1;                  // B k-half
    const int xorB = (rowB >> 1) & 3;           // invariant under +16

    load_stage(0, 0); CP_COMMIT();
    load_stage(1, 1); CP_COMMIT();

    for (int c = 0; c < NC; c++) {
        CP_WAIT1();
        __syncthreads();

        const uint32_t base = sb32 + (uint32_t)((c % 3) * STG_B);
        #pragma unroll
        for (int ks = 0; ks < 2; ks++) {
            uint32_t ah[2][4], al[2][4];
            const uint32_t acol = (uint32_t)(((ks * 2 + kha) ^ xorA) * 16);
            #pragma unroll
            for (int mt = 0; mt < 2; mt++) {
                const uint32_t ad = base + (uint32_t)((rowA + mt * 16) * 64) + acol;
                ldm_x4(ah[mt], ad);                 // AH
                ldm_x4(al[mt], ad + MAT_B);         // AL
            }
            const uint32_t bcol = (uint32_t)(((ks * 2 + khb) ^ xorB) * 16);
            #pragma unroll
            for (int pair = 0; pair < 4; pair++) {
                const uint32_t bd = base + 2 * MAT_B + (uint32_t)((rowB + pair * 16) * 64) + bcol;
                uint32_t bh[4], bl[4];
                ldm_x4(bh, bd);
                ldm_x4(bl, bd + MAT_B);
                #pragma unroll
                for (int mt = 0; mt < 2; mt++) {
                    #pragma unroll
                    for (int nt = 0; nt < 2; nt++) {
                        float* d = acc[mt][pair * 2 + nt];
                        mma_bf16(d, ah[mt], bh[nt * 2], bh[nt * 2 + 1]);
                        mma_bf16(d, ah[mt], bl[nt * 2], bl[nt * 2 + 1]);
                        mma_bf16(d, al[mt], bh[nt * 2], bh[nt * 2 + 1]);
                    }
                }
            }
        }
        __syncthreads();
        if (c + 2 < NC) load_stage((c + 2) % 3, c + 2);
        CP_COMMIT();
    }

    // ---- epilogue ----
    #pragma unroll
    for (int mt = 0; mt < 2; mt++) {
        const int r = bm + wm * 32 + mt * 16 + (lane >> 2);
        #pragma unroll
        for (int j = 0; j < 8; j++) {
            const int col = bn + wn * 64 + j * 8 + (lane & 3) * 2;
            const float bx = bias[col], by = bias[col + 1];
            if (r < M) {
                float2 o = make_float2(acc[mt][j][0] + bx, acc[mt][j][1] + by);
                *reinterpret_cast<float2*>(&C[(size_t)r * N + col]) = o;
            }
            if (r + 8 < M) {
                float2 o = make_float2(acc[mt][j][2] + bx, acc[mt][j][3] + by);
                *reinterpret_cast<float2*>(&C[(size_t)(r + 8) * N + col]) = o;
            }
        }
    }
}

// ===================== attention kernels (passing since R2) ================
__global__ __launch_bounds__(256)
void temporal_kernel(const float* __restrict__ Pq, const float* __restrict__ Pk,
                     const float* __restrict__ Pv, float* __restrict__ tmpf)
{
    const int p = blockIdx.x + 1;
    const int b = blockIdx.y / NHc;
    const int h = blockIdx.y % NHc;
    const int tid = threadIdx.x;

    __shared__ float qs[NFc][D3c + 1];
    __shared__ float ks[NFc][D3c + 1];
    __shared__ float vs[NFc][D3c + 1];
    __shared__ float logits[NFc][NFc + 1];
    __shared__ float colw[NFc];

    for (int e = tid; e < NFc * 96; e += 256) {
        const int f = e / 96;
        const int i = e % 96;
        const int t = f * NPc + p;
        const size_t base = ((size_t)(b * SEQ1 + 1 + t)) * N3D + h * D3c + 2 * i;
        float q0 = Pq[base], q1 = Pq[base + 1];
        float k0 = Pv[base], k1 = Pv[base + 1];
        const float v0 = Pk[base], v1 = Pk[base + 1];
        if (i < 32) {
            const double invf = pow(10000.0, -(double)(2 * i) / 64.0);
            const double a = (double)t * invf;
            const float c = (float)cos(a);
            const float s = (float)sin(a);
            const float nq0 = q0 * c - q1 * s, nq1 = q1 * c + q0 * s;
            const float nk0 = k0 * c - k1 * s, nk1 = k1 * c + k0 * s;
            q0 = nq0; q1 = nq1; k0 = nk0; k1 = nk1;
        }
        qs[f][2 * i] = q0; qs[f][2 * i + 1] = q1;
        ks[f][2 * i] = k0; ks[f][2 * i + 1] = k1;
        vs[f][2 * i] = v0; vs[f][2 * i + 1] = v1;
    }
    __syncthreads();

    {
        const int f = tid >> 4, g = tid & 15;
        float d = 0.f;
        #pragma unroll 8
        for (int e = 0; e < D3c; e++) d += qs[f][e] * ks[g][e];
        logits[f][g] = d * SCALEc;
    }
    __syncthreads();

    if (tid < NFc) {
        const int f = tid;
        float m = -1e30f;
        #pragma unroll
        for (int g = 0; g < NFc; g++) m = fmaxf(m, logits[f][g]);
        float l = 0.f;
        #pragma unroll
        for (int g = 0; g < NFc; g++) l += expf(logits[f][g] - m);
        const float inv = 1.f / l;
        #pragma unroll
        for (int g = 0; g < NFc; g++) logits[f][g] = expf(logits[f][g] - m) * inv;
    }
    __syncthreads();

    if (tid < NFc) {
        const int g = tid;
        float s = 0.f;
        #pragma unroll
        for (int f = 0; f < NFc; f++) s += logits[f][g];
        colw[g] = s;
    }
    __syncthreads();

    if (tid < D3c) {
        const int d = tid;
        float a = 0.f;
        #pragma unroll
        for (int g = 0; g < NFc; g++) a += colw[g] * vs[g][d];
        tmpf[((size_t)(b * 195 + (p - 1))) * N3D + h * D3c + d] = a;
    }
}

__global__ __launch_bounds__(256)
void cls_kernel(const float* __restrict__ Pq, const float* __restrict__ Pk,
                const float* __restrict__ Pv, float* __restrict__ t2cat)
{
    const int b = blockIdx.x / NHc;
    const int h = blockIdx.x % NHc;
    const int tid = threadIdx.x;

    __shared__ float logits[SEQ1];
    __shared__ float qv[D3c];
    __shared__ float red[256];

    if (tid < D3c) qv[tid] = Pq[((size_t)(b * SEQ1)) * N3D + h * D3c + tid];
    __syncthreads();

    float lmax = -1e30f;
    for (int s = tid; s < SEQ1; s += 256) {
        const float* kr = Pk + ((size_t)(b * SEQ1 + s)) * N3D + h * D3c;
        float d = 0.f;
        #pragma unroll 8
        for (int e = 0; e < D3c; e++) d += qv[e] * kr[e];
        d *= SCALEc;
        logits[s] = d;
        lmax = fmaxf(lmax, d);
    }
    red[tid] = lmax; __syncthreads();
    for (int o = 128; o > 0; o >>= 1) { if (tid < o) red[tid] = fmaxf(red[tid], red[tid + o]); __syncthreads(); }
    const float M = red[0];
    __syncthreads();

    float lsum = 0.f;
    for (int s = tid; s < SEQ1; s += 256) {
        const float w = expf(logits[s] - M);
        logits[s] = w;
        lsum += w;
    }
    red[tid] = lsum; __syncthreads();
    for (int o = 128; o > 0; o >>= 1) { if (tid < o) red[tid] += red[tid + o]; __syncthreads(); }
    const float inv = 1.f / red[0];
    __syncthreads();

    if (tid < D3c) {
        float a = 0.f;
        for (int s = 0; s < SEQ1; s++)
            a += logits[s] * Pv[((size_t)(b * SEQ1 + s)) * N3D + h * D3c + tid];
        t2cat[((size_t)(b * 17)) * N3D + h * D3c + tid] = a * inv;
    }
}

__global__ __launch_bounds__(256)
void spatial_kernel(const float* __restrict__ q2u, const float* __restrict__ k2u,
                    const float* __restrict__ v2u, float* __restrict__ t2cat)
{
    const int xi = blockIdx.x;
    const int b = blockIdx.y / NHc;
    const int h = blockIdx.y % NHc;
    const int tid = threadIdx.x;
    const int warp = tid >> 5, lane = tid & 31;
    const int nk = (xi == 0) ? 196 : 16;
    const int hb = h * D3c;

    __shared__ float wsh[8][200];
    __shared__ float wacc[8][D3c];

    for (int e = tid; e < 8 * D3c; e += 256) wacc[e / D3c][e % D3c] = 0.f;
    __syncthreads();

    for (int q0 = warp; q0 < 196; q0 += 8) {
        const int qp = (xi + q0) % 195;
        const float* qr = q2u + ((size_t)(b * 195 + qp)) * N3D + hb;

        float lg[7];
        float lmax = -1e30f;
        int cnt = 0;
        for (int m = lane; m < nk; m += 32) {
            const int kp = (xi == 0) ? (m % 195) : ((xi + m) % 195);
            const float* kr = k2u + ((size_t)(b * 195 + kp)) * N3D + hb;
            float d = 0.f;
            #pragma unroll 8
            for (int e = 0; e < D3c; e++) d += qr[e] * kr[e];
            lg[cnt++] = d * SCALEc;
            lmax = fmaxf(lmax, d * SCALEc);
        }
        #pragma unroll
        for (int o = 16; o > 0; o >>= 1) lmax = fmaxf(lmax, __shfl_xor_sync(0xffffffffu, lmax, o));
        float lsum = 0.f;
        for (int c = 0; c < cnt; c++) { lg[c] = expf(lg[c] - lmax); lsum += lg[c]; }
        #pragma unroll
        for (int o = 16; o > 0; o >>= 1) lsum += __shfl_xor_sync(0xffffffffu, lsum, o);
        const float inv = 1.f / lsum;
        cnt = 0;
        for (int m = lane; m < nk; m += 32) wsh[warp][m] = lg[cnt++] * inv;
        __syncwarp();

        for (int dd = lane; dd < D3c; dd += 32) {
            float a = 0.f;
            for (int m = 0; m < nk; m++) {
                const int kp = (xi == 0) ? (m % 195) : ((xi + m) % 195);
                a += wsh[warp][m] * v2u[((size_t)(b * 195 + kp)) * N3D + hb + dd];
            }
            wacc[warp][dd] += a;
        }
        __syncwarp();
    }
    __syncthreads();

    if (tid < D3c) {
        float s = 0.f;
        #pragma unroll
        for (int wp = 0; wp < 8; wp++) s += wacc[wp][tid];
        t2cat[((size_t)(b * 17) + 1 + xi) * N3D + hb + tid] = s;
    }
}

__global__ void broadcast_kernel(const float* __restrict__ outsmall, float* __restrict__ out)
{
    const size_t i = (size_t)blockIdx.x * blockDim.x + threadIdx.x;
    const size_t total = (size_t)Bc * SEQ1 * DIMc;
    if (i >= total) return;
    const int c = (int)(i % DIMc);
    const size_t bs = i / DIMc;
    const int s = (int)(bs % SEQ1);
    const int b = (int)(bs / SEQ1);
    const int r = (s == 0) ? 0 : (1 + ((s - 1) & 15));
    out[i] = outsmall[((size_t)(b * 17) + r) * DIMc + c];
}

// ===================== launch ==============================================
extern "C" void kernel_launch(void* const* d_in, const int* in_sizes, int n_in,
                              void* d_out, int out_size)
{
    const float* x  = (const float*)d_in[0];
    const float* Wq = (const float*)d_in[1];
    const float* bq = (const float*)d_in[2];
    const float* Wk = (const float*)d_in[3];
    const float* bk = (const float*)d_in[4];
    const float* Wv = (const float*)d_in[5];
    const float* bv = (const float*)d_in[6];
    const float* Wt = (const float*)d_in[7];
    const float* bt = (const float*)d_in[8];
    const float* Wf = (const float*)d_in[9];
    const float* bf = (const float*)d_in[10];
    float* out = (float*)d_out;

    float *Pq, *Pk, *Pv, *tmpf, *ti, *q2u, *k2u, *v2u, *t2cat, *outsmall;
    __nv_bfloat16 *Ah, *Al, *Wqh, *Wql, *Wkh, *Wkl, *Wvh, *Wvl, *Wth, *Wtl, *Wfh, *Wfl;
    cudaGetSymbolAddress((void**)&Pq, g_Pq);
    cudaGetSymbolAddress((void**)&Pk, g_Pk);
    cudaGetSymbolAddress((void**)&Pv, g_Pv);
    cudaGetSymbolAddress((void**)&tmpf, g_tmp);
    cudaGetSymbolAddress((void**)&ti, g_ti);
    cudaGetSymbolAddress((void**)&q2u, g_q2u);
    cudaGetSymbolAddress((void**)&k2u, g_k2u);
    cudaGetSymbolAddress((void**)&v2u, g_v2u);
    cudaGetSymbolAddress((void**)&t2cat, g_t2cat);
    cudaGetSymbolAddress((void**)&outsmall, g_outsmall);
    cudaGetSymbolAddress((void**)&Ah, g_Ah);
    cudaGetSymbolAddress((void**)&Al, g_Al);
    cudaGetSymbolAddress((void**)&Wqh, g_Wqh); cudaGetSymbolAddress((void**)&Wql, g_Wql);
    cudaGetSymbolAddress((void**)&Wkh, g_Wkh); cudaGetSymbolAddress((void**)&Wkl, g_Wkl);
    cudaGetSymbolAddress((void**)&Wvh, g_Wvh); cudaGetSymbolAddress((void**)&Wvl, g_Wvl);
    cudaGetSymbolAddress((void**)&Wth, g_Wth); cudaGetSymbolAddress((void**)&Wtl, g_Wtl);
    cudaGetSymbolAddress((void**)&Wfh, g_Wfh); cudaGetSymbolAddress((void**)&Wfl, g_Wfl);

    cudaFuncSetAttribute(gemm_bf16s, cudaFuncAttributeMaxDynamicSharedMemorySize, GEMM_SMEM);

    const dim3 blk(256);

    // 0) weight prep: transpose + split to bf16 hi/lo [N][K]
    transpose_split<<<dim3(DIMc / 32, N3D / 32), blk>>>(Wq, Wqh, Wql, DIMc, N3D);
    transpose_split<<<dim3(DIMc / 32, N3D / 32), blk>>>(Wk, Wkh, Wkl, DIMc, N3D);
    transpose_split<<<dim3(DIMc / 32, N3D / 32), blk>>>(Wv, Wvh, Wvl, DIMc, N3D);
    transpose_split<<<dim3(N3D / 32, DIMc / 32), blk>>>(Wt, Wth, Wtl, N3D, DIMc);
    transpose_split<<<dim3(N3D / 32, DIMc / 32), blk>>>(Wf, Wfh, Wfl, N3D, DIMc);

    // 1) QKV projections
    {
        const int n4 = MROWS * DIMc / 4;
        split_f32<<<(n4 + 255) / 256, blk>>>(x, Ah, Al, n4);
        gemm_bf16s<<<dim3(N3D / GBN, (MROWS + GBM - 1) / GBM, 3), blk, GEMM_SMEM>>>(
            Ah, Al, Wqh, Wql, Wkh, Wkl, Wvh, Wvl, bq, bk, bv, Pq, Pk, Pv, MROWS, N3D, DIMc);
    }

    // 2) temporal + cls attention
    temporal_kernel<<<dim3(195, Bc * NHc), blk>>>(Pq, Pk, Pv, tmpf);
    cls_kernel<<<Bc * NHc, blk>>>(Pq, Pk, Pv, t2cat);

    // 3) ti = tmp @ Wt + bt
    {
        const int n4 = Bc * 195 * N3D / 4;
        split_f32<<<(n4 + 255) / 256, blk>>>(tmpf, Ah, Al, n4);
        gemm_bf16s<<<dim3(DIMc / GBN, (Bc * 195 + GBM - 1) / GBM, 1), blk, GEMM_SMEM>>>(
            Ah, Al, Wth, Wtl, Wth, Wtl, Wth, Wtl, bt, bt, bt, ti, ti, ti, Bc * 195, DIMc, N3D);
    }

    // 4) second-stage projections (crossed k/v per reference)
    {
        const int n4 = Bc * 195 * DIMc / 4;
        split_f32<<<(n4 + 255) / 256, blk>>>(ti, Ah, Al, n4);
        gemm_bf16s<<<dim3(N3D / GBN, (Bc * 195 + GBM - 1) / GBM, 3), blk, GEMM_SMEM>>>(
            Ah, Al, Wqh, Wql, Wvh, Wvl, Wkh, Wkl, bq, bv, bk, q2u, k2u, v2u, Bc * 195, N3D, DIMc);
    }

    // 5) spatial attention
    spatial_kernel<<<dim3(16, Bc * NHc), blk>>>(q2u, k2u, v2u, t2cat);

    // 6) final projection of 17 unique rows per batch
    {
        const int n4 = Bc * 17 * N3D / 4;
        split_f32<<<(n4 + 255) / 256, blk>>>(t2cat, Ah, Al, n4);
        gemm_bf16s<<<dim3(DIMc / GBN, (Bc * 17 + GBM - 1) / GBM, 1), blk, GEMM_SMEM>>>(
            Ah, Al, Wfh, Wfl, Wfh, Wfl, Wfh, Wfl, bf, bf, bf, outsmall, outsmall, outsmall, Bc * 17, DIMc, N3D);
    }

    // 7) broadcast to full output
    const size_t total = (size_t)Bc * SEQ1 * DIMc;
    broadcast_kernel<<<(unsigned)((total + 255) / 256), blk>>>(outsmall, out);
}